// round 11
// baseline (speedup 1.0000x reference)
#include <cuda_runtime.h>

// LSTMModel: B=1024, T=256, I=5, H=64, L=3, O=1, fp32.
// R10: R9 + hoisted gate activations in lstm_rec. Thread t activates its own
// gate column in-register right after the GEMM (warp-uniform MUFU type,
// overlaps GEMM tail across warps); gates_s now holds ACTIVATED gates, so the
// post-barrier cell chain is just LDS x4 + FMA + tanh(c) + mul.
// Bitwise-identical math to R9.

#define B_SZ 1024
#define T_SZ 256
#define I_SZ 5
#define H_SZ 64
#define G_SZ 256   // 4*H
#define N4   112           // CTAs carrying 4 rows; rest carry 3
#define GRID_REC 304       // 112*4 + 192*3 = 1024

typedef unsigned long long u64;

__device__ float g_xg[(size_t)B_SZ * T_SZ * G_SZ];  // gate preactivations (layers 1,2)
__device__ float g_h [(size_t)B_SZ * T_SZ * H_SZ];  // layer outputs
__device__ float g_wT1[H_SZ * G_SZ];                // transposed w_ih1
__device__ float g_wT2[H_SZ * G_SZ];                // transposed w_ih2

__device__ __forceinline__ u64 ffma2(u64 a, u64 b, u64 c) {
    u64 d;
    asm("fma.rn.f32x2 %0, %1, %2, %3;" : "=l"(d) : "l"(a), "l"(b), "l"(c));
    return d;
}
__device__ __forceinline__ u64 pack2(float lo, float hi) {
    u64 d;
    asm("mov.b64 %0, {%1, %2};" : "=l"(d) : "f"(lo), "f"(hi));
    return d;
}
__device__ __forceinline__ float sum2(u64 v) {
    float lo, hi;
    asm("mov.b64 {%0, %1}, %2;" : "=f"(lo), "=f"(hi) : "l"(v));
    return lo + hi;
}

__device__ __forceinline__ float sigf(float x) {
    return __fdividef(1.0f, 1.0f + __expf(-x));
}
__device__ __forceinline__ float tanh_fast(float x) {
    float ax = fabsf(x);
    float e  = __expf(-2.0f * ax);
    float r  = __fdividef(1.0f - e, 1.0f + e);
    return copysignf(r, x);
}

// ---------------------------------------------------------------------------
// Transpose w_ih1 AND w_ih2 [256,64] -> g_wT1/g_wT2 [64,256] in one launch.
// ---------------------------------------------------------------------------
__global__ __launch_bounds__(256) void transpose_w2(
    const float* __restrict__ w1, const float* __restrict__ w2)
{
    int idx = blockIdx.x * 256 + threadIdx.x;  // < 32768
    int l = idx >> 14, r = idx & 16383;
    int g = r >> 6, k = r & 63;
    if (l == 0) g_wT1[k * G_SZ + g] = w1[r];
    else        g_wT2[k * G_SZ + g] = w2[r];
}

// ---------------------------------------------------------------------------
// Layers 1/2 input projection (R9-exact: conflict-free b-reads).
// ---------------------------------------------------------------------------
#define XG_W_PITCH 260
#define XG_SMEM_BYTES (64 * 64 * 8 + 64 * XG_W_PITCH * 4)

__global__ __launch_bounds__(256, 2) void xg_gemm64(
    const float* __restrict__ b_ih, const float* __restrict__ b_hh, int which)
{
    extern __shared__ __align__(16) unsigned char smraw[];
    u64   (*a2_s)[64]        = (u64(*)[64])smraw;                      // 32 KB
    float (*w_s)[XG_W_PITCH] = (float(*)[XG_W_PITCH])(smraw + 64 * 64 * 8);
    const float* wT = which ? g_wT2 : g_wT1;

    const int t    = threadIdx.x;
    const int row0 = blockIdx.x * 64;
    const int tcol = t & 31, trow = t >> 5;
    const int gA   = 4 * tcol;
    const int gB   = 128 + 4 * tcol;

#pragma unroll
    for (int u = 0; u < 4; u++) {
        int v = u * 256 + t;
        int r = v >> 4, kq = v & 15;
        float4 d = *(const float4*)&g_h[(size_t)(row0 + r) * H_SZ + kq * 4];
        ulonglong2 e0, e1;
        e0.x = pack2(d.x, d.x); e0.y = pack2(d.y, d.y);
        e1.x = pack2(d.z, d.z); e1.y = pack2(d.w, d.w);
        *(ulonglong2*)&a2_s[r][kq * 4]     = e0;
        *(ulonglong2*)&a2_s[r][kq * 4 + 2] = e1;
    }
#pragma unroll
    for (int u = 0; u < 16; u++) {
        int v = u * 256 + t;
        int k = v >> 6, gq = v & 63;
        float4 d = *(const float4*)&wT[k * G_SZ + gq * 4];
        *(float4*)&w_s[k][gq * 4] = d;
    }

    u64 acc2[8][4];
    {
        u64 bp[4];
#pragma unroll
        for (int p = 0; p < 2; p++) {
            bp[p]     = pack2(b_ih[gA + 2 * p]     + b_hh[gA + 2 * p],
                              b_ih[gA + 2 * p + 1] + b_hh[gA + 2 * p + 1]);
            bp[2 + p] = pack2(b_ih[gB + 2 * p]     + b_hh[gB + 2 * p],
                              b_ih[gB + 2 * p + 1] + b_hh[gB + 2 * p + 1]);
        }
#pragma unroll
        for (int ii = 0; ii < 8; ii++)
#pragma unroll
            for (int jp = 0; jp < 4; jp++) acc2[ii][jp] = bp[jp];
    }

    __syncthreads();

#pragma unroll 4
    for (int k = 0; k < 64; k++) {
        u64 adup[8];
#pragma unroll
        for (int ii = 0; ii < 8; ii++)
            adup[ii] = a2_s[trow * 8 + ii][k];
        ulonglong2 bvA = *(const ulonglong2*)&w_s[k][gA];
        ulonglong2 bvB = *(const ulonglong2*)&w_s[k][gB];
        u64 bp[4] = {bvA.x, bvA.y, bvB.x, bvB.y};
#pragma unroll
        for (int ii = 0; ii < 8; ii++)
#pragma unroll
            for (int jp = 0; jp < 4; jp++)
                acc2[ii][jp] = ffma2(adup[ii], bp[jp], acc2[ii][jp]);
    }

#pragma unroll
    for (int ii = 0; ii < 8; ii++) {
        size_t base = (size_t)(row0 + trow * 8 + ii) * G_SZ;
        ulonglong2 oA, oB;
        oA.x = acc2[ii][0]; oA.y = acc2[ii][1];
        oB.x = acc2[ii][2]; oB.y = acc2[ii][3];
        *(ulonglong2*)&g_xg[base + gA] = oA;
        *(ulonglong2*)&g_xg[base + gB] = oB;
    }
}

// ---------------------------------------------------------------------------
// Recurrent scan: R9 structure + hoisted activations. gates_s holds ACTIVATED
// gates. Thread t's gate type = t>>6 (warp-uniform): 2=tanh, else sigmoid.
// ---------------------------------------------------------------------------
__global__ __launch_bounds__(256, 2) void lstm_rec(
    const float* __restrict__ w_hh,
    const float* __restrict__ x,      // mode 0 only
    const float* __restrict__ w_ih,   // mode 0 only [256,5]
    const float* __restrict__ b_ih,   // mode 0 only
    const float* __restrict__ b_hh,   // mode 0 only
    const float* __restrict__ wfc,    // mode 2 only
    const float* __restrict__ bfc,    // mode 2 only
    float* __restrict__ out,          // mode 2 only
    int mode)
{
    __shared__ __align__(16) float h_s[4][H_SZ];     // 1 KB
    __shared__ float gates_s[4][G_SZ];               // 4 KB (activated)
    __shared__ float xs[2][4][8];                    // mode-0 x staging
    const int t   = threadIdx.x;                     // gate column
    const int bid = blockIdx.x;
    const bool r4 = (bid < N4);
    const int b0  = r4 ? bid * 4 : N4 * 4 + (bid - N4) * 3;
    const int rows = r4 ? 4 : 3;
    const bool is_g = ((t >> 6) == 2);               // warp-uniform gate type

    // register-resident recurrent weight pairs (w_hh row t)
    u64 w2[32];
    {
        const ulonglong2* wv = (const ulonglong2*)(w_hh + t * H_SZ);
#pragma unroll
        for (int q = 0; q < 16; q++) {
            ulonglong2 v = wv[q];
            w2[2 * q]     = v.x;
            w2[2 * q + 1] = v.y;
        }
    }

    // mode-0: input weights + bias + step-0 x staging
    float wx[I_SZ];
    float bias = 0.0f;
    if (mode == 0) {
#pragma unroll
        for (int k = 0; k < I_SZ; k++) wx[k] = w_ih[t * I_SZ + k];
        bias = b_ih[t] + b_hh[t];
        if (t < 4 * I_SZ) {
            int r = t / I_SZ, k = t % I_SZ;
            if (r < rows)
                xs[0][r][k] = x[((size_t)(b0 + r) * T_SZ) * I_SZ + k];
        }
    }

    ((float*)h_s)[t] = 0.0f;

    const int re = t >> 6, je = t & 63;
    const bool cell = (t < rows * 64);
    float c = 0.0f;
    float h_last = 0.0f;

    float xn[4];
    if (mode != 0) {
#pragma unroll
        for (int r = 0; r < 3; r++)
            xn[r] = g_xg[((size_t)(b0 + r) * T_SZ) * G_SZ + t];
        xn[3] = r4 ? g_xg[((size_t)(b0 + 3) * T_SZ) * G_SZ + t] : 0.0f;
    }

    __syncthreads();

    for (int step = 0; step < T_SZ; step++) {
        u64 acc2[4];
        if (mode == 0) {
            const int cur = step & 1;
            float a0 = bias, a1 = bias, a2v = bias, a3 = bias;
#pragma unroll
            for (int k = 0; k < I_SZ; k++) {
                a0  = fmaf(xs[cur][0][k], wx[k], a0);
                a1  = fmaf(xs[cur][1][k], wx[k], a1);
                a2v = fmaf(xs[cur][2][k], wx[k], a2v);
                a3  = fmaf(xs[cur][3][k], wx[k], a3);
            }
            acc2[0] = pack2(a0, 0.0f);  acc2[1] = pack2(a1, 0.0f);
            acc2[2] = pack2(a2v, 0.0f); acc2[3] = pack2(a3, 0.0f);
            if (step + 1 < T_SZ && t < 4 * I_SZ) {
                int r = t / I_SZ, k = t % I_SZ;
                if (r < rows)
                    xs[cur ^ 1][r][k] = x[((size_t)(b0 + r) * T_SZ + step + 1) * I_SZ + k];
            }
        } else {
#pragma unroll
            for (int r = 0; r < 4; r++) acc2[r] = pack2(xn[r], 0.0f);
            if (step + 1 < T_SZ) {
#pragma unroll
                for (int r = 0; r < 3; r++)
                    xn[r] = g_xg[((size_t)(b0 + r) * T_SZ + step + 1) * G_SZ + t];
                if (r4)
                    xn[3] = g_xg[((size_t)(b0 + 3) * T_SZ + step + 1) * G_SZ + t];
            }
        }

        // GEMM: gates[r][t] += sum_k h[r][k] * w_hh[t][k]
        const ulonglong2* h2 = (const ulonglong2*)&h_s[0][0];
#pragma unroll
        for (int q = 0; q < 16; q++) {
            const u64 wa = w2[2 * q], wb = w2[2 * q + 1];
            ulonglong2 p0 = h2[q];
            acc2[0] = ffma2(p0.x, wa, acc2[0]);
            acc2[0] = ffma2(p0.y, wb, acc2[0]);
            ulonglong2 p1 = h2[16 + q];
            acc2[1] = ffma2(p1.x, wa, acc2[1]);
            acc2[1] = ffma2(p1.y, wb, acc2[1]);
            ulonglong2 p2 = h2[32 + q];
            acc2[2] = ffma2(p2.x, wa, acc2[2]);
            acc2[2] = ffma2(p2.y, wb, acc2[2]);
        }
        if (r4) {
#pragma unroll
            for (int q = 0; q < 16; q++) {
                ulonglong2 p3 = h2[48 + q];
                acc2[3] = ffma2(p3.x, w2[2 * q],     acc2[3]);
                acc2[3] = ffma2(p3.y, w2[2 * q + 1], acc2[3]);
            }
        }

        // hoisted activation: thread t activates its own gate column for all
        // rows (warp-uniform branch; MUFUs overlap GEMM tail across warps)
        {
            float v0 = sum2(acc2[0]);
            float v1 = sum2(acc2[1]);
            float v2 = sum2(acc2[2]);
            if (is_g) {
                gates_s[0][t] = tanh_fast(v0);
                gates_s[1][t] = tanh_fast(v1);
                gates_s[2][t] = tanh_fast(v2);
                if (r4) gates_s[3][t] = tanh_fast(sum2(acc2[3]));
            } else {
                gates_s[0][t] = sigf(v0);
                gates_s[1][t] = sigf(v1);
                gates_s[2][t] = sigf(v2);
                if (r4) gates_s[3][t] = sigf(sum2(acc2[3]));
            }
        }
        __syncthreads();

        // cell update: gates already activated -> short chain
        if (cell) {
            float iv = gates_s[re][je];
            float fv = gates_s[re][64 + je];
            float gv = gates_s[re][128 + je];
            float ov = gates_s[re][192 + je];
            c = fmaf(fv, c, iv * gv);
            float hv = ov * tanh_fast(c);
            h_s[re][je] = hv;
            h_last = hv;
            if (mode != 2)
                g_h[((size_t)(b0 + re) * T_SZ + step) * H_SZ + je] = hv;
        }
        __syncthreads();
    }

    // mode 2: fused FC — out[b0+re] = sum_je h_last*wfc[je] + bfc[0]
    if (mode == 2) {
        float p = cell ? h_last * wfc[je] : 0.0f;
#pragma unroll
        for (int off = 16; off; off >>= 1)
            p += __shfl_down_sync(0xFFFFFFFFu, p, off);
        if ((t & 31) == 0) gates_s[0][t >> 5] = p;   // one value per warp
        __syncthreads();
        if (t < rows)
            out[b0 + t] = gates_s[0][2 * t] + gates_s[0][2 * t + 1] + bfc[0];
    }
}

// ---------------------------------------------------------------------------
extern "C" void kernel_launch(void* const* d_in, const int* in_sizes, int n_in,
                              void* d_out, int out_size)
{
    (void)in_sizes; (void)n_in; (void)out_size;
    const float* x     = (const float*)d_in[0];
    const float* w_ih0 = (const float*)d_in[1];
    const float* w_hh0 = (const float*)d_in[2];
    const float* b_ih0 = (const float*)d_in[3];
    const float* b_hh0 = (const float*)d_in[4];
    const float* w_ih1 = (const float*)d_in[5];
    const float* w_hh1 = (const float*)d_in[6];
    const float* b_ih1 = (const float*)d_in[7];
    const float* b_hh1 = (const float*)d_in[8];
    const float* w_ih2 = (const float*)d_in[9];
    const float* w_hh2 = (const float*)d_in[10];
    const float* b_ih2 = (const float*)d_in[11];
    const float* b_hh2 = (const float*)d_in[12];
    const float* w_fc  = (const float*)d_in[13];
    const float* b_fc  = (const float*)d_in[14];
    float* out = (float*)d_out;

    const int NROWS = B_SZ * T_SZ;  // 262144

    cudaFuncSetAttribute(xg_gemm64, cudaFuncAttributeMaxDynamicSharedMemorySize,
                         XG_SMEM_BYTES);

    // both weight transposes upfront
    transpose_w2<<<128, 256>>>(w_ih1, w_ih2);

    // layer 0 (xg fused into rec)
    lstm_rec<<<GRID_REC, 256>>>(w_hh0, x, w_ih0, b_ih0, b_hh0,
                                nullptr, nullptr, nullptr, 0);

    // layer 1
    xg_gemm64<<<NROWS / 64, 256, XG_SMEM_BYTES>>>(b_ih1, b_hh1, 0);
    lstm_rec<<<GRID_REC, 256>>>(w_hh1, nullptr, nullptr, nullptr, nullptr,
                                nullptr, nullptr, nullptr, 1);

    // layer 2 (+ fused FC)
    xg_gemm64<<<NROWS / 64, 256, XG_SMEM_BYTES>>>(b_ih2, b_hh2, 1);
    lstm_rec<<<GRID_REC, 256>>>(w_hh2, nullptr, nullptr, nullptr, nullptr,
                                w_fc, b_fc, out, 2);
}

// round 12
// speedup vs baseline: 1.0088x; 1.0088x over previous
#include <cuda_runtime.h>

// LSTMModel: B=1024, T=256, I=5, H=64, L=3, O=1, fp32.
// R11: R10 (hoisted activations) + sigmoids via single-instruction
// tanh.approx.f32: sigma(x) = 0.5*tanh(0.5x)+0.5 (1 MUFU + mul + fma vs
// EX2+RCP chain). g-gate tanh and tanh(c) stay on the exact EX2/RCP path
// to bound accumulated state error. MUFU/cell: 10 -> 7.

#define B_SZ 1024
#define T_SZ 256
#define I_SZ 5
#define H_SZ 64
#define G_SZ 256   // 4*H
#define N4   112           // CTAs carrying 4 rows; rest carry 3
#define GRID_REC 304       // 112*4 + 192*3 = 1024

typedef unsigned long long u64;

__device__ float g_xg[(size_t)B_SZ * T_SZ * G_SZ];  // gate preactivations (layers 1,2)
__device__ float g_h [(size_t)B_SZ * T_SZ * H_SZ];  // layer outputs
__device__ float g_wT1[H_SZ * G_SZ];                // transposed w_ih1
__device__ float g_wT2[H_SZ * G_SZ];                // transposed w_ih2

__device__ __forceinline__ u64 ffma2(u64 a, u64 b, u64 c) {
    u64 d;
    asm("fma.rn.f32x2 %0, %1, %2, %3;" : "=l"(d) : "l"(a), "l"(b), "l"(c));
    return d;
}
__device__ __forceinline__ u64 pack2(float lo, float hi) {
    u64 d;
    asm("mov.b64 %0, {%1, %2};" : "=l"(d) : "f"(lo), "f"(hi));
    return d;
}
__device__ __forceinline__ float sum2(u64 v) {
    float lo, hi;
    asm("mov.b64 {%0, %1}, %2;" : "=f"(lo), "=f"(hi) : "l"(v));
    return lo + hi;
}

// sigmoid via MUFU.TANH: sigma(x) = 0.5*tanh(x/2) + 0.5
__device__ __forceinline__ float sig_t(float x) {
    float y = 0.5f * x, t;
    asm("tanh.approx.f32 %0, %1;" : "=f"(t) : "f"(y));
    return fmaf(0.5f, t, 0.5f);
}
// exact-path tanh (EX2+RCP), used for g gate and tanh(c)
__device__ __forceinline__ float tanh_fast(float x) {
    float ax = fabsf(x);
    float e  = __expf(-2.0f * ax);
    float r  = __fdividef(1.0f - e, 1.0f + e);
    return copysignf(r, x);
}

// ---------------------------------------------------------------------------
// Transpose w_ih1 AND w_ih2 [256,64] -> g_wT1/g_wT2 [64,256] in one launch.
// ---------------------------------------------------------------------------
__global__ __launch_bounds__(256) void transpose_w2(
    const float* __restrict__ w1, const float* __restrict__ w2)
{
    int idx = blockIdx.x * 256 + threadIdx.x;  // < 32768
    int l = idx >> 14, r = idx & 16383;
    int g = r >> 6, k = r & 63;
    if (l == 0) g_wT1[k * G_SZ + g] = w1[r];
    else        g_wT2[k * G_SZ + g] = w2[r];
}

// ---------------------------------------------------------------------------
// Layers 1/2 input projection (R9-exact: conflict-free b-reads).
// ---------------------------------------------------------------------------
#define XG_W_PITCH 260
#define XG_SMEM_BYTES (64 * 64 * 8 + 64 * XG_W_PITCH * 4)

__global__ __launch_bounds__(256, 2) void xg_gemm64(
    const float* __restrict__ b_ih, const float* __restrict__ b_hh, int which)
{
    extern __shared__ __align__(16) unsigned char smraw[];
    u64   (*a2_s)[64]        = (u64(*)[64])smraw;                      // 32 KB
    float (*w_s)[XG_W_PITCH] = (float(*)[XG_W_PITCH])(smraw + 64 * 64 * 8);
    const float* wT = which ? g_wT2 : g_wT1;

    const int t    = threadIdx.x;
    const int row0 = blockIdx.x * 64;
    const int tcol = t & 31, trow = t >> 5;
    const int gA   = 4 * tcol;
    const int gB   = 128 + 4 * tcol;

#pragma unroll
    for (int u = 0; u < 4; u++) {
        int v = u * 256 + t;
        int r = v >> 4, kq = v & 15;
        float4 d = *(const float4*)&g_h[(size_t)(row0 + r) * H_SZ + kq * 4];
        ulonglong2 e0, e1;
        e0.x = pack2(d.x, d.x); e0.y = pack2(d.y, d.y);
        e1.x = pack2(d.z, d.z); e1.y = pack2(d.w, d.w);
        *(ulonglong2*)&a2_s[r][kq * 4]     = e0;
        *(ulonglong2*)&a2_s[r][kq * 4 + 2] = e1;
    }
#pragma unroll
    for (int u = 0; u < 16; u++) {
        int v = u * 256 + t;
        int k = v >> 6, gq = v & 63;
        float4 d = *(const float4*)&wT[k * G_SZ + gq * 4];
        *(float4*)&w_s[k][gq * 4] = d;
    }

    u64 acc2[8][4];
    {
        u64 bp[4];
#pragma unroll
        for (int p = 0; p < 2; p++) {
            bp[p]     = pack2(b_ih[gA + 2 * p]     + b_hh[gA + 2 * p],
                              b_ih[gA + 2 * p + 1] + b_hh[gA + 2 * p + 1]);
            bp[2 + p] = pack2(b_ih[gB + 2 * p]     + b_hh[gB + 2 * p],
                              b_ih[gB + 2 * p + 1] + b_hh[gB + 2 * p + 1]);
        }
#pragma unroll
        for (int ii = 0; ii < 8; ii++)
#pragma unroll
            for (int jp = 0; jp < 4; jp++) acc2[ii][jp] = bp[jp];
    }

    __syncthreads();

#pragma unroll 4
    for (int k = 0; k < 64; k++) {
        u64 adup[8];
#pragma unroll
        for (int ii = 0; ii < 8; ii++)
            adup[ii] = a2_s[trow * 8 + ii][k];
        ulonglong2 bvA = *(const ulonglong2*)&w_s[k][gA];
        ulonglong2 bvB = *(const ulonglong2*)&w_s[k][gB];
        u64 bp[4] = {bvA.x, bvA.y, bvB.x, bvB.y};
#pragma unroll
        for (int ii = 0; ii < 8; ii++)
#pragma unroll
            for (int jp = 0; jp < 4; jp++)
                acc2[ii][jp] = ffma2(adup[ii], bp[jp], acc2[ii][jp]);
    }

#pragma unroll
    for (int ii = 0; ii < 8; ii++) {
        size_t base = (size_t)(row0 + trow * 8 + ii) * G_SZ;
        ulonglong2 oA, oB;
        oA.x = acc2[ii][0]; oA.y = acc2[ii][1];
        oB.x = acc2[ii][2]; oB.y = acc2[ii][3];
        *(ulonglong2*)&g_xg[base + gA] = oA;
        *(ulonglong2*)&g_xg[base + gB] = oB;
    }
}

// ---------------------------------------------------------------------------
// Recurrent scan: R10 structure (hoisted activations; gates_s ACTIVATED).
// Thread t's gate type = t>>6 (warp-uniform): 2=tanh(exact), else sig_t.
// ---------------------------------------------------------------------------
__global__ __launch_bounds__(256, 2) void lstm_rec(
    const float* __restrict__ w_hh,
    const float* __restrict__ x,      // mode 0 only
    const float* __restrict__ w_ih,   // mode 0 only [256,5]
    const float* __restrict__ b_ih,   // mode 0 only
    const float* __restrict__ b_hh,   // mode 0 only
    const float* __restrict__ wfc,    // mode 2 only
    const float* __restrict__ bfc,    // mode 2 only
    float* __restrict__ out,          // mode 2 only
    int mode)
{
    __shared__ __align__(16) float h_s[4][H_SZ];     // 1 KB
    __shared__ float gates_s[4][G_SZ];               // 4 KB (activated)
    __shared__ float xs[2][4][8];                    // mode-0 x staging
    const int t   = threadIdx.x;                     // gate column
    const int bid = blockIdx.x;
    const bool r4 = (bid < N4);
    const int b0  = r4 ? bid * 4 : N4 * 4 + (bid - N4) * 3;
    const int rows = r4 ? 4 : 3;
    const bool is_g = ((t >> 6) == 2);               // warp-uniform gate type

    // register-resident recurrent weight pairs (w_hh row t)
    u64 w2[32];
    {
        const ulonglong2* wv = (const ulonglong2*)(w_hh + t * H_SZ);
#pragma unroll
        for (int q = 0; q < 16; q++) {
            ulonglong2 v = wv[q];
            w2[2 * q]     = v.x;
            w2[2 * q + 1] = v.y;
        }
    }

    // mode-0: input weights + bias + step-0 x staging
    float wx[I_SZ];
    float bias = 0.0f;
    if (mode == 0) {
#pragma unroll
        for (int k = 0; k < I_SZ; k++) wx[k] = w_ih[t * I_SZ + k];
        bias = b_ih[t] + b_hh[t];
        if (t < 4 * I_SZ) {
            int r = t / I_SZ, k = t % I_SZ;
            if (r < rows)
                xs[0][r][k] = x[((size_t)(b0 + r) * T_SZ) * I_SZ + k];
        }
    }

    ((float*)h_s)[t] = 0.0f;

    const int re = t >> 6, je = t & 63;
    const bool cell = (t < rows * 64);
    float c = 0.0f;
    float h_last = 0.0f;

    float xn[4];
    if (mode != 0) {
#pragma unroll
        for (int r = 0; r < 3; r++)
            xn[r] = g_xg[((size_t)(b0 + r) * T_SZ) * G_SZ + t];
        xn[3] = r4 ? g_xg[((size_t)(b0 + 3) * T_SZ) * G_SZ + t] : 0.0f;
    }

    __syncthreads();

    for (int step = 0; step < T_SZ; step++) {
        u64 acc2[4];
        if (mode == 0) {
            const int cur = step & 1;
            float a0 = bias, a1 = bias, a2v = bias, a3 = bias;
#pragma unroll
            for (int k = 0; k < I_SZ; k++) {
                a0  = fmaf(xs[cur][0][k], wx[k], a0);
                a1  = fmaf(xs[cur][1][k], wx[k], a1);
                a2v = fmaf(xs[cur][2][k], wx[k], a2v);
                a3  = fmaf(xs[cur][3][k], wx[k], a3);
            }
            acc2[0] = pack2(a0, 0.0f);  acc2[1] = pack2(a1, 0.0f);
            acc2[2] = pack2(a2v, 0.0f); acc2[3] = pack2(a3, 0.0f);
            if (step + 1 < T_SZ && t < 4 * I_SZ) {
                int r = t / I_SZ, k = t % I_SZ;
                if (r < rows)
                    xs[cur ^ 1][r][k] = x[((size_t)(b0 + r) * T_SZ + step + 1) * I_SZ + k];
            }
        } else {
#pragma unroll
            for (int r = 0; r < 4; r++) acc2[r] = pack2(xn[r], 0.0f);
            if (step + 1 < T_SZ) {
#pragma unroll
                for (int r = 0; r < 3; r++)
                    xn[r] = g_xg[((size_t)(b0 + r) * T_SZ + step + 1) * G_SZ + t];
                if (r4)
                    xn[3] = g_xg[((size_t)(b0 + 3) * T_SZ + step + 1) * G_SZ + t];
            }
        }

        // GEMM: gates[r][t] += sum_k h[r][k] * w_hh[t][k]
        const ulonglong2* h2 = (const ulonglong2*)&h_s[0][0];
#pragma unroll
        for (int q = 0; q < 16; q++) {
            const u64 wa = w2[2 * q], wb = w2[2 * q + 1];
            ulonglong2 p0 = h2[q];
            acc2[0] = ffma2(p0.x, wa, acc2[0]);
            acc2[0] = ffma2(p0.y, wb, acc2[0]);
            ulonglong2 p1 = h2[16 + q];
            acc2[1] = ffma2(p1.x, wa, acc2[1]);
            acc2[1] = ffma2(p1.y, wb, acc2[1]);
            ulonglong2 p2 = h2[32 + q];
            acc2[2] = ffma2(p2.x, wa, acc2[2]);
            acc2[2] = ffma2(p2.y, wb, acc2[2]);
        }
        if (r4) {
#pragma unroll
            for (int q = 0; q < 16; q++) {
                ulonglong2 p3 = h2[48 + q];
                acc2[3] = ffma2(p3.x, w2[2 * q],     acc2[3]);
                acc2[3] = ffma2(p3.y, w2[2 * q + 1], acc2[3]);
            }
        }

        // hoisted activation (warp-uniform gate type)
        {
            float v0 = sum2(acc2[0]);
            float v1 = sum2(acc2[1]);
            float v2 = sum2(acc2[2]);
            if (is_g) {
                gates_s[0][t] = tanh_fast(v0);
                gates_s[1][t] = tanh_fast(v1);
                gates_s[2][t] = tanh_fast(v2);
                if (r4) gates_s[3][t] = tanh_fast(sum2(acc2[3]));
            } else {
                gates_s[0][t] = sig_t(v0);
                gates_s[1][t] = sig_t(v1);
                gates_s[2][t] = sig_t(v2);
                if (r4) gates_s[3][t] = sig_t(sum2(acc2[3]));
            }
        }
        __syncthreads();

        // cell update: gates already activated -> short chain
        if (cell) {
            float iv = gates_s[re][je];
            float fv = gates_s[re][64 + je];
            float gv = gates_s[re][128 + je];
            float ov = gates_s[re][192 + je];
            c = fmaf(fv, c, iv * gv);
            float hv = ov * tanh_fast(c);
            h_s[re][je] = hv;
            h_last = hv;
            if (mode != 2)
                g_h[((size_t)(b0 + re) * T_SZ + step) * H_SZ + je] = hv;
        }
        __syncthreads();
    }

    // mode 2: fused FC — out[b0+re] = sum_je h_last*wfc[je] + bfc[0]
    if (mode == 2) {
        float p = cell ? h_last * wfc[je] : 0.0f;
#pragma unroll
        for (int off = 16; off; off >>= 1)
            p += __shfl_down_sync(0xFFFFFFFFu, p, off);
        if ((t & 31) == 0) gates_s[0][t >> 5] = p;   // one value per warp
        __syncthreads();
        if (t < rows)
            out[b0 + t] = gates_s[0][2 * t] + gates_s[0][2 * t + 1] + bfc[0];
    }
}

// ---------------------------------------------------------------------------
extern "C" void kernel_launch(void* const* d_in, const int* in_sizes, int n_in,
                              void* d_out, int out_size)
{
    (void)in_sizes; (void)n_in; (void)out_size;
    const float* x     = (const float*)d_in[0];
    const float* w_ih0 = (const float*)d_in[1];
    const float* w_hh0 = (const float*)d_in[2];
    const float* b_ih0 = (const float*)d_in[3];
    const float* b_hh0 = (const float*)d_in[4];
    const float* w_ih1 = (const float*)d_in[5];
    const float* w_hh1 = (const float*)d_in[6];
    const float* b_ih1 = (const float*)d_in[7];
    const float* b_hh1 = (const float*)d_in[8];
    const float* w_ih2 = (const float*)d_in[9];
    const float* w_hh2 = (const float*)d_in[10];
    const float* b_ih2 = (const float*)d_in[11];
    const float* b_hh2 = (const float*)d_in[12];
    const float* w_fc  = (const float*)d_in[13];
    const float* b_fc  = (const float*)d_in[14];
    float* out = (float*)d_out;

    const int NROWS = B_SZ * T_SZ;  // 262144

    cudaFuncSetAttribute(xg_gemm64, cudaFuncAttributeMaxDynamicSharedMemorySize,
                         XG_SMEM_BYTES);

    // both weight transposes upfront
    transpose_w2<<<128, 256>>>(w_ih1, w_ih2);

    // layer 0 (xg fused into rec)
    lstm_rec<<<GRID_REC, 256>>>(w_hh0, x, w_ih0, b_ih0, b_hh0,
                                nullptr, nullptr, nullptr, 0);

    // layer 1
    xg_gemm64<<<NROWS / 64, 256, XG_SMEM_BYTES>>>(b_ih1, b_hh1, 0);
    lstm_rec<<<GRID_REC, 256>>>(w_hh1, nullptr, nullptr, nullptr, nullptr,
                                nullptr, nullptr, nullptr, 1);

    // layer 2 (+ fused FC)
    xg_gemm64<<<NROWS / 64, 256, XG_SMEM_BYTES>>>(b_ih2, b_hh2, 1);
    lstm_rec<<<GRID_REC, 256>>>(w_hh2, nullptr, nullptr, nullptr, nullptr,
                                w_fc, b_fc, out, 2);
}

// round 13
// speedup vs baseline: 1.0412x; 1.0321x over previous
#include <cuda_runtime.h>

// LSTMModel: B=1024, T=256, I=5, H=64, L=3, O=1, fp32.
// R12: R11 + ALL activations on single-instruction MUFU.TANH:
//   sigma(x) = 0.5*tanh(0.5x)+0.5, tanh = tanh.approx.f32 (g gate AND
//   tanh(c) in the cell chain). MUFU/cell: 7 -> 5; post-barrier serial
//   tail loses the EX2->RCP->div chain (~40cyc -> 16cyc).

#define B_SZ 1024
#define T_SZ 256
#define I_SZ 5
#define H_SZ 64
#define G_SZ 256   // 4*H
#define N4   112           // CTAs carrying 4 rows; rest carry 3
#define GRID_REC 304       // 112*4 + 192*3 = 1024

typedef unsigned long long u64;

__device__ float g_xg[(size_t)B_SZ * T_SZ * G_SZ];  // gate preactivations (layers 1,2)
__device__ float g_h [(size_t)B_SZ * T_SZ * H_SZ];  // layer outputs
__device__ float g_wT1[H_SZ * G_SZ];                // transposed w_ih1
__device__ float g_wT2[H_SZ * G_SZ];                // transposed w_ih2

__device__ __forceinline__ u64 ffma2(u64 a, u64 b, u64 c) {
    u64 d;
    asm("fma.rn.f32x2 %0, %1, %2, %3;" : "=l"(d) : "l"(a), "l"(b), "l"(c));
    return d;
}
__device__ __forceinline__ u64 pack2(float lo, float hi) {
    u64 d;
    asm("mov.b64 %0, {%1, %2};" : "=l"(d) : "f"(lo), "f"(hi));
    return d;
}
__device__ __forceinline__ float sum2(u64 v) {
    float lo, hi;
    asm("mov.b64 {%0, %1}, %2;" : "=f"(lo), "=f"(hi) : "l"(v));
    return lo + hi;
}

// single-instruction tanh (MUFU.TANH)
__device__ __forceinline__ float tanh_a(float x) {
    float t;
    asm("tanh.approx.f32 %0, %1;" : "=f"(t) : "f"(x));
    return t;
}
// sigmoid via MUFU.TANH: sigma(x) = 0.5*tanh(x/2) + 0.5
__device__ __forceinline__ float sig_t(float x) {
    return fmaf(0.5f, tanh_a(0.5f * x), 0.5f);
}

// ---------------------------------------------------------------------------
// Transpose w_ih1 AND w_ih2 [256,64] -> g_wT1/g_wT2 [64,256] in one launch.
// ---------------------------------------------------------------------------
__global__ __launch_bounds__(256) void transpose_w2(
    const float* __restrict__ w1, const float* __restrict__ w2)
{
    int idx = blockIdx.x * 256 + threadIdx.x;  // < 32768
    int l = idx >> 14, r = idx & 16383;
    int g = r >> 6, k = r & 63;
    if (l == 0) g_wT1[k * G_SZ + g] = w1[r];
    else        g_wT2[k * G_SZ + g] = w2[r];
}

// ---------------------------------------------------------------------------
// Layers 1/2 input projection (R9-exact: conflict-free b-reads).
// ---------------------------------------------------------------------------
#define XG_W_PITCH 260
#define XG_SMEM_BYTES (64 * 64 * 8 + 64 * XG_W_PITCH * 4)

__global__ __launch_bounds__(256, 2) void xg_gemm64(
    const float* __restrict__ b_ih, const float* __restrict__ b_hh, int which)
{
    extern __shared__ __align__(16) unsigned char smraw[];
    u64   (*a2_s)[64]        = (u64(*)[64])smraw;                      // 32 KB
    float (*w_s)[XG_W_PITCH] = (float(*)[XG_W_PITCH])(smraw + 64 * 64 * 8);
    const float* wT = which ? g_wT2 : g_wT1;

    const int t    = threadIdx.x;
    const int row0 = blockIdx.x * 64;
    const int tcol = t & 31, trow = t >> 5;
    const int gA   = 4 * tcol;
    const int gB   = 128 + 4 * tcol;

#pragma unroll
    for (int u = 0; u < 4; u++) {
        int v = u * 256 + t;
        int r = v >> 4, kq = v & 15;
        float4 d = *(const float4*)&g_h[(size_t)(row0 + r) * H_SZ + kq * 4];
        ulonglong2 e0, e1;
        e0.x = pack2(d.x, d.x); e0.y = pack2(d.y, d.y);
        e1.x = pack2(d.z, d.z); e1.y = pack2(d.w, d.w);
        *(ulonglong2*)&a2_s[r][kq * 4]     = e0;
        *(ulonglong2*)&a2_s[r][kq * 4 + 2] = e1;
    }
#pragma unroll
    for (int u = 0; u < 16; u++) {
        int v = u * 256 + t;
        int k = v >> 6, gq = v & 63;
        float4 d = *(const float4*)&wT[k * G_SZ + gq * 4];
        *(float4*)&w_s[k][gq * 4] = d;
    }

    u64 acc2[8][4];
    {
        u64 bp[4];
#pragma unroll
        for (int p = 0; p < 2; p++) {
            bp[p]     = pack2(b_ih[gA + 2 * p]     + b_hh[gA + 2 * p],
                              b_ih[gA + 2 * p + 1] + b_hh[gA + 2 * p + 1]);
            bp[2 + p] = pack2(b_ih[gB + 2 * p]     + b_hh[gB + 2 * p],
                              b_ih[gB + 2 * p + 1] + b_hh[gB + 2 * p + 1]);
        }
#pragma unroll
        for (int ii = 0; ii < 8; ii++)
#pragma unroll
            for (int jp = 0; jp < 4; jp++) acc2[ii][jp] = bp[jp];
    }

    __syncthreads();

#pragma unroll 4
    for (int k = 0; k < 64; k++) {
        u64 adup[8];
#pragma unroll
        for (int ii = 0; ii < 8; ii++)
            adup[ii] = a2_s[trow * 8 + ii][k];
        ulonglong2 bvA = *(const ulonglong2*)&w_s[k][gA];
        ulonglong2 bvB = *(const ulonglong2*)&w_s[k][gB];
        u64 bp[4] = {bvA.x, bvA.y, bvB.x, bvB.y};
#pragma unroll
        for (int ii = 0; ii < 8; ii++)
#pragma unroll
            for (int jp = 0; jp < 4; jp++)
                acc2[ii][jp] = ffma2(adup[ii], bp[jp], acc2[ii][jp]);
    }

#pragma unroll
    for (int ii = 0; ii < 8; ii++) {
        size_t base = (size_t)(row0 + trow * 8 + ii) * G_SZ;
        ulonglong2 oA, oB;
        oA.x = acc2[ii][0]; oA.y = acc2[ii][1];
        oB.x = acc2[ii][2]; oB.y = acc2[ii][3];
        *(ulonglong2*)&g_xg[base + gA] = oA;
        *(ulonglong2*)&g_xg[base + gB] = oB;
    }
}

// ---------------------------------------------------------------------------
// Recurrent scan: hoisted activations (gates_s ACTIVATED), all-MUFU.TANH.
// ---------------------------------------------------------------------------
__global__ __launch_bounds__(256, 2) void lstm_rec(
    const float* __restrict__ w_hh,
    const float* __restrict__ x,      // mode 0 only
    const float* __restrict__ w_ih,   // mode 0 only [256,5]
    const float* __restrict__ b_ih,   // mode 0 only
    const float* __restrict__ b_hh,   // mode 0 only
    const float* __restrict__ wfc,    // mode 2 only
    const float* __restrict__ bfc,    // mode 2 only
    float* __restrict__ out,          // mode 2 only
    int mode)
{
    __shared__ __align__(16) float h_s[4][H_SZ];     // 1 KB
    __shared__ float gates_s[4][G_SZ];               // 4 KB (activated)
    __shared__ float xs[2][4][8];                    // mode-0 x staging
    const int t   = threadIdx.x;                     // gate column
    const int bid = blockIdx.x;
    const bool r4 = (bid < N4);
    const int b0  = r4 ? bid * 4 : N4 * 4 + (bid - N4) * 3;
    const int rows = r4 ? 4 : 3;
    const bool is_g = ((t >> 6) == 2);               // warp-uniform gate type

    // register-resident recurrent weight pairs (w_hh row t)
    u64 w2[32];
    {
        const ulonglong2* wv = (const ulonglong2*)(w_hh + t * H_SZ);
#pragma unroll
        for (int q = 0; q < 16; q++) {
            ulonglong2 v = wv[q];
            w2[2 * q]     = v.x;
            w2[2 * q + 1] = v.y;
        }
    }

    // mode-0: input weights + bias + step-0 x staging
    float wx[I_SZ];
    float bias = 0.0f;
    if (mode == 0) {
#pragma unroll
        for (int k = 0; k < I_SZ; k++) wx[k] = w_ih[t * I_SZ + k];
        bias = b_ih[t] + b_hh[t];
        if (t < 4 * I_SZ) {
            int r = t / I_SZ, k = t % I_SZ;
            if (r < rows)
                xs[0][r][k] = x[((size_t)(b0 + r) * T_SZ) * I_SZ + k];
        }
    }

    ((float*)h_s)[t] = 0.0f;

    const int re = t >> 6, je = t & 63;
    const bool cell = (t < rows * 64);
    float c = 0.0f;
    float h_last = 0.0f;

    float xn[4];
    if (mode != 0) {
#pragma unroll
        for (int r = 0; r < 3; r++)
            xn[r] = g_xg[((size_t)(b0 + r) * T_SZ) * G_SZ + t];
        xn[3] = r4 ? g_xg[((size_t)(b0 + 3) * T_SZ) * G_SZ + t] : 0.0f;
    }

    __syncthreads();

    for (int step = 0; step < T_SZ; step++) {
        u64 acc2[4];
        if (mode == 0) {
            const int cur = step & 1;
            float a0 = bias, a1 = bias, a2v = bias, a3 = bias;
#pragma unroll
            for (int k = 0; k < I_SZ; k++) {
                a0  = fmaf(xs[cur][0][k], wx[k], a0);
                a1  = fmaf(xs[cur][1][k], wx[k], a1);
                a2v = fmaf(xs[cur][2][k], wx[k], a2v);
                a3  = fmaf(xs[cur][3][k], wx[k], a3);
            }
            acc2[0] = pack2(a0, 0.0f);  acc2[1] = pack2(a1, 0.0f);
            acc2[2] = pack2(a2v, 0.0f); acc2[3] = pack2(a3, 0.0f);
            if (step + 1 < T_SZ && t < 4 * I_SZ) {
                int r = t / I_SZ, k = t % I_SZ;
                if (r < rows)
                    xs[cur ^ 1][r][k] = x[((size_t)(b0 + r) * T_SZ + step + 1) * I_SZ + k];
            }
        } else {
#pragma unroll
            for (int r = 0; r < 4; r++) acc2[r] = pack2(xn[r], 0.0f);
            if (step + 1 < T_SZ) {
#pragma unroll
                for (int r = 0; r < 3; r++)
                    xn[r] = g_xg[((size_t)(b0 + r) * T_SZ + step + 1) * G_SZ + t];
                if (r4)
                    xn[3] = g_xg[((size_t)(b0 + 3) * T_SZ + step + 1) * G_SZ + t];
            }
        }

        // GEMM: gates[r][t] += sum_k h[r][k] * w_hh[t][k]
        const ulonglong2* h2 = (const ulonglong2*)&h_s[0][0];
#pragma unroll
        for (int q = 0; q < 16; q++) {
            const u64 wa = w2[2 * q], wb = w2[2 * q + 1];
            ulonglong2 p0 = h2[q];
            acc2[0] = ffma2(p0.x, wa, acc2[0]);
            acc2[0] = ffma2(p0.y, wb, acc2[0]);
            ulonglong2 p1 = h2[16 + q];
            acc2[1] = ffma2(p1.x, wa, acc2[1]);
            acc2[1] = ffma2(p1.y, wb, acc2[1]);
            ulonglong2 p2 = h2[32 + q];
            acc2[2] = ffma2(p2.x, wa, acc2[2]);
            acc2[2] = ffma2(p2.y, wb, acc2[2]);
        }
        if (r4) {
#pragma unroll
            for (int q = 0; q < 16; q++) {
                ulonglong2 p3 = h2[48 + q];
                acc2[3] = ffma2(p3.x, w2[2 * q],     acc2[3]);
                acc2[3] = ffma2(p3.y, w2[2 * q + 1], acc2[3]);
            }
        }

        // hoisted activation (warp-uniform gate type; all MUFU.TANH)
        {
            float v0 = sum2(acc2[0]);
            float v1 = sum2(acc2[1]);
            float v2 = sum2(acc2[2]);
            if (is_g) {
                gates_s[0][t] = tanh_a(v0);
                gates_s[1][t] = tanh_a(v1);
                gates_s[2][t] = tanh_a(v2);
                if (r4) gates_s[3][t] = tanh_a(sum2(acc2[3]));
            } else {
                gates_s[0][t] = sig_t(v0);
                gates_s[1][t] = sig_t(v1);
                gates_s[2][t] = sig_t(v2);
                if (r4) gates_s[3][t] = sig_t(sum2(acc2[3]));
            }
        }
        __syncthreads();

        // cell update: gates activated -> short chain (single MUFU.TANH)
        if (cell) {
            float iv = gates_s[re][je];
            float fv = gates_s[re][64 + je];
            float gv = gates_s[re][128 + je];
            float ov = gates_s[re][192 + je];
            c = fmaf(fv, c, iv * gv);
            float hv = ov * tanh_a(c);
            h_s[re][je] = hv;
            h_last = hv;
            if (mode != 2)
                g_h[((size_t)(b0 + re) * T_SZ + step) * H_SZ + je] = hv;
        }
        __syncthreads();
    }

    // mode 2: fused FC — out[b0+re] = sum_je h_last*wfc[je] + bfc[0]
    if (mode == 2) {
        float p = cell ? h_last * wfc[je] : 0.0f;
#pragma unroll
        for (int off = 16; off; off >>= 1)
            p += __shfl_down_sync(0xFFFFFFFFu, p, off);
        if ((t & 31) == 0) gates_s[0][t >> 5] = p;   // one value per warp
        __syncthreads();
        if (t < rows)
            out[b0 + t] = gates_s[0][2 * t] + gates_s[0][2 * t + 1] + bfc[0];
    }
}

// ---------------------------------------------------------------------------
extern "C" void kernel_launch(void* const* d_in, const int* in_sizes, int n_in,
                              void* d_out, int out_size)
{
    (void)in_sizes; (void)n_in; (void)out_size;
    const float* x     = (const float*)d_in[0];
    const float* w_ih0 = (const float*)d_in[1];
    const float* w_hh0 = (const float*)d_in[2];
    const float* b_ih0 = (const float*)d_in[3];
    const float* b_hh0 = (const float*)d_in[4];
    const float* w_ih1 = (const float*)d_in[5];
    const float* w_hh1 = (const float*)d_in[6];
    const float* b_ih1 = (const float*)d_in[7];
    const float* b_hh1 = (const float*)d_in[8];
    const float* w_ih2 = (const float*)d_in[9];
    const float* w_hh2 = (const float*)d_in[10];
    const float* b_ih2 = (const float*)d_in[11];
    const float* b_hh2 = (const float*)d_in[12];
    const float* w_fc  = (const float*)d_in[13];
    const float* b_fc  = (const float*)d_in[14];
    float* out = (float*)d_out;

    const int NROWS = B_SZ * T_SZ;  // 262144

    cudaFuncSetAttribute(xg_gemm64, cudaFuncAttributeMaxDynamicSharedMemorySize,
                         XG_SMEM_BYTES);

    // both weight transposes upfront
    transpose_w2<<<128, 256>>>(w_ih1, w_ih2);

    // layer 0 (xg fused into rec)
    lstm_rec<<<GRID_REC, 256>>>(w_hh0, x, w_ih0, b_ih0, b_hh0,
                                nullptr, nullptr, nullptr, 0);

    // layer 1
    xg_gemm64<<<NROWS / 64, 256, XG_SMEM_BYTES>>>(b_ih1, b_hh1, 0);
    lstm_rec<<<GRID_REC, 256>>>(w_hh1, nullptr, nullptr, nullptr, nullptr,
                                nullptr, nullptr, nullptr, 1);

    // layer 2 (+ fused FC)
    xg_gemm64<<<NROWS / 64, 256, XG_SMEM_BYTES>>>(b_ih2, b_hh2, 1);
    lstm_rec<<<GRID_REC, 256>>>(w_hh2, nullptr, nullptr, nullptr, nullptr,
                                w_fc, b_fc, out, 2);
}